// round 4
// baseline (speedup 1.0000x reference)
#include <cuda_runtime.h>
#include <cstdint>

// ---------------- problem constants ----------------
#define NB      8
#define LQ      2500
#define DM      256
#define NH      8
#define NL      4
#define NP      8
#define NZ      4
#define DH      32
#define LEN_IN  14960

// scratch
__device__ float g_value[(size_t)NB * LEN_IN * DM];           // 119680 x 256
__device__ float g_off  [(size_t)NB * LQ * NH * NL * NP * 2]; // 20000 x 512
__device__ float g_awl  [(size_t)NB * LQ * NH * NL * NP];     // 20000 x 256

__device__ __forceinline__ float to_tf32(float x) {
    float r;
    asm("cvt.rna.tf32.f32 %0, %1;" : "=f"(r) : "f"(x));
    return r;
}

__device__ __forceinline__ uint32_t smem_u32(const void* p) {
    return (uint32_t)__cvta_generic_to_shared(p);
}

__device__ __forceinline__ void cp_async16(void* dst, const void* src, bool pred) {
    int sz = pred ? 16 : 0;
    asm volatile("cp.async.ca.shared.global [%0], [%1], 16, %2;\n"
                 :: "r"(smem_u32(dst)), "l"(src), "r"(sz));
}

// ---------------- merged tf32 GEMM: 3 independent GEMMs in one launch ----------------
struct GemmSeg {
    const float* A; const float* B; const float* bias; float* C;
    int M, N, K, tilesX, blockStart;
};
struct GemmParams { GemmSeg s[3]; };

#define A_LD 20     // A smem row stride (floats)
#define B_LD 136    // B smem row stride (floats)
#define A_BUF (128 * A_LD)
#define B_BUF (16 * B_LD)

__global__ __launch_bounds__(256)
void gemm_tf32_multi(GemmParams p)
{
    __shared__ float As[2 * A_BUF];   // [buf][m][k] rows of 16 (pad 20)
    __shared__ float Bs[2 * B_BUF];   // [buf][k][n] rows of 128 (pad 136)

    const int bx = blockIdx.x;
    const int si = (bx >= p.s[1].blockStart ? 1 : 0) + (bx >= p.s[2].blockStart ? 1 : 0);
    const GemmSeg sg = p.s[si];
    const int local = bx - sg.blockStart;
    const int row0  = (local / sg.tilesX) * 128;
    const int col0  = (local % sg.tilesX) * 128;
    const int M = sg.M, N = sg.N, K = sg.K;
    const float* __restrict__ A = sg.A;
    const float* __restrict__ B = sg.B;

    const int tid   = threadIdx.x;
    const int warp  = tid >> 5;
    const int lane  = tid & 31;
    const int g     = lane >> 2;
    const int tig   = lane & 3;
    const int mrow  = (warp & 3) * 32;
    const int ncol  = (warp >> 2) * 64;

    float acc[2][8][4];
#pragma unroll
    for (int i = 0; i < 2; i++)
#pragma unroll
        for (int j = 0; j < 8; j++)
#pragma unroll
            for (int c = 0; c < 4; c++) acc[i][j][c] = 0.f;

    const int a_r0 = tid >> 2, a_c = (tid & 3) << 2;
    const int b_r0 = tid >> 5, b_c = (tid & 31) << 2;

    const int nkt = K / 16;

    auto stage = [&](int kt, int buf) {
        float* ab = As + buf * A_BUF;
        float* bb = Bs + buf * B_BUF;
#pragma unroll
        for (int i = 0; i < 2; i++) {
            int ar = a_r0 + i * 64;
            int gr = row0 + ar;
            cp_async16(&ab[ar * A_LD + a_c],
                       &A[(size_t)min(gr, M - 1) * K + kt * 16 + a_c], gr < M);
            int br = b_r0 + i * 8;
            cp_async16(&bb[br * B_LD + b_c],
                       &B[(size_t)(kt * 16 + br) * N + col0 + b_c], true);
        }
    };

    stage(0, 0);
    asm volatile("cp.async.commit_group;\n");

    for (int kt = 0; kt < nkt; kt++) {
        int cb = kt & 1;
        if (kt + 1 < nkt) stage(kt + 1, cb ^ 1);
        asm volatile("cp.async.commit_group;\n");
        asm volatile("cp.async.wait_group 1;\n");
        __syncthreads();

        const float* ab = As + cb * A_BUF;
        const float* bb = Bs + cb * B_BUF;
#pragma unroll
        for (int ks = 0; ks < 2; ks++) {
            const int k0 = ks * 8;
            uint32_t afr[2][4];
#pragma unroll
            for (int mt = 0; mt < 2; mt++) {
                int rb = mrow + mt * 16;
                afr[mt][0] = __float_as_uint(to_tf32(ab[(rb + g    ) * A_LD + k0 + tig    ]));
                afr[mt][1] = __float_as_uint(to_tf32(ab[(rb + g + 8) * A_LD + k0 + tig    ]));
                afr[mt][2] = __float_as_uint(to_tf32(ab[(rb + g    ) * A_LD + k0 + tig + 4]));
                afr[mt][3] = __float_as_uint(to_tf32(ab[(rb + g + 8) * A_LD + k0 + tig + 4]));
            }
            uint32_t bfr[8][2];
#pragma unroll
            for (int nt = 0; nt < 8; nt++) {
                int cbn = ncol + nt * 8;
                bfr[nt][0] = __float_as_uint(to_tf32(bb[(k0 + tig    ) * B_LD + cbn + g]));
                bfr[nt][1] = __float_as_uint(to_tf32(bb[(k0 + tig + 4) * B_LD + cbn + g]));
            }
#pragma unroll
            for (int mt = 0; mt < 2; mt++)
#pragma unroll
                for (int nt = 0; nt < 8; nt++) {
                    asm volatile(
                        "mma.sync.aligned.m16n8k8.row.col.f32.tf32.tf32.f32 "
                        "{%0,%1,%2,%3}, {%4,%5,%6,%7}, {%8,%9}, {%0,%1,%2,%3};"
                        : "+f"(acc[mt][nt][0]), "+f"(acc[mt][nt][1]),
                          "+f"(acc[mt][nt][2]), "+f"(acc[mt][nt][3])
                        : "r"(afr[mt][0]), "r"(afr[mt][1]),
                          "r"(afr[mt][2]), "r"(afr[mt][3]),
                          "r"(bfr[nt][0]), "r"(bfr[nt][1]));
                }
        }
        __syncthreads();
    }

    // epilogue
#pragma unroll
    for (int mt = 0; mt < 2; mt++) {
#pragma unroll
        for (int nt = 0; nt < 8; nt++) {
            int c = col0 + ncol + nt * 8 + tig * 2;
            float b0 = sg.bias[c], b1 = sg.bias[c + 1];
            int r0 = row0 + mrow + mt * 16 + g;
            if (r0 < M) {
                float2 v0 = make_float2(acc[mt][nt][0] + b0, acc[mt][nt][1] + b1);
                *(float2*)&sg.C[(size_t)r0 * N + c] = v0;
            }
            int r1 = r0 + 8;
            if (r1 < M) {
                float2 v1 = make_float2(acc[mt][nt][2] + b0, acc[mt][nt][3] + b1);
                *(float2*)&sg.C[(size_t)r1 * N + c] = v1;
            }
        }
    }
}

// ---------------- fused softmax + bilinear sampling (v4) ----------------
// One warp per (n, q, h). Gather phase: lane = (q4: point-subgroup) x (c8: channel quad).
// 4 independent corner accumulators; corner loads batched before FMAs for MLP.
__global__ __launch_bounds__(256)
void msda_sample4(const float* __restrict__ value,
                  const float* __restrict__ off,
                  const float* __restrict__ awl,
                  const float* __restrict__ refp,
                  float* __restrict__ out)
{
    const unsigned FULL = 0xffffffffu;
    int gwarp = (blockIdx.x * blockDim.x + threadIdx.x) >> 5;
    int lane  = threadIdx.x & 31;
    if (gwarp >= NB * LQ * NH) return;

    int h  = gwarp % NH;
    int nq = gwarp / NH;
    int n  = nq / LQ;

    // softmax over 32 logits (lane = point index)
    float logit = awl[(size_t)nq * (NH * NL * NP) + h * (NL * NP) + lane];
    float m = logit;
#pragma unroll
    for (int s = 16; s > 0; s >>= 1) m = fmaxf(m, __shfl_xor_sync(FULL, m, s));
    float e = __expf(logit - m);
    float ssum = e;
#pragma unroll
    for (int s = 16; s > 0; s >>= 1) ssum += __shfl_xor_sync(FULL, ssum, s);
    float aw = e / ssum;

    // per-point precompute (lane p == point p: level l = lane>>3, z = lane&3)
    float2 o2 = ((const float2*)(off + (size_t)nq * (NH * NL * NP * 2) + h * (NL * NP * 2)))[lane];
    int l = lane >> 3;
    float2 r2 = ((const float2*)(refp + (size_t)nq * NZ * 2))[lane & 3];
    int W = 176 >> l;
    int H = 64 >> l;
    int St = ((l > 0) ? 11264 : 0) + ((l > 1) ? 2816 : 0) + ((l > 2) ? 704 : 0);

    float x = fmaf(r2.x, (float)W, o2.x) - 0.5f;
    float y = fmaf(r2.y, (float)H, o2.y) - 0.5f;
    float xf = floorf(x), yf = floorf(y);
    int x0 = (int)xf, y0 = (int)yf;
    float wx = x - xf, wy = y - yf;
    float w00 = (1.f - wx) * (1.f - wy) * aw;
    float w01 = wx * (1.f - wy) * aw;
    float w10 = (1.f - wx) * wy * aw;
    float w11 = wx * wy * aw;

    bool ix0 = ((unsigned)x0       < (unsigned)W);
    bool ix1 = ((unsigned)(x0 + 1) < (unsigned)W);
    bool iy0 = ((unsigned)y0       < (unsigned)H);
    bool iy1 = ((unsigned)(y0 + 1) < (unsigned)H);

    int i00 = 0, i01 = 0, i10 = 0, i11 = 0;     // float4-granule indices
    if (ix0 && iy0) i00 = (St + y0 * W + x0) * (DM / 4);           else w00 = 0.f;
    if (ix1 && iy0) i01 = (St + y0 * W + x0 + 1) * (DM / 4);       else w01 = 0.f;
    if (ix0 && iy1) i10 = (St + (y0 + 1) * W + x0) * (DM / 4);     else w10 = 0.f;
    if (ix1 && iy1) i11 = (St + (y0 + 1) * W + x0 + 1) * (DM / 4); else w11 = 0.f;

    // gather phase: lane = q4*8 + c8
    int q4 = lane >> 3;
    int c8 = lane & 7;
    const float4* vb4 = (const float4*)(value + (size_t)n * LEN_IN * DM + h * DH) + c8;

    float4 a0 = make_float4(0.f, 0.f, 0.f, 0.f);
    float4 a1 = make_float4(0.f, 0.f, 0.f, 0.f);
    float4 a2 = make_float4(0.f, 0.f, 0.f, 0.f);
    float4 a3 = make_float4(0.f, 0.f, 0.f, 0.f);

#pragma unroll
    for (int pb = 0; pb < 32; pb += 4) {
        int src = pb + q4;
        int j0 = __shfl_sync(FULL, i00, src);
        int j1 = __shfl_sync(FULL, i01, src);
        int j2 = __shfl_sync(FULL, i10, src);
        int j3 = __shfl_sync(FULL, i11, src);
        float u0 = __shfl_sync(FULL, w00, src);
        float u1 = __shfl_sync(FULL, w01, src);
        float u2 = __shfl_sync(FULL, w10, src);
        float u3 = __shfl_sync(FULL, w11, src);
        float4 v0 = __ldg(vb4 + j0);
        float4 v1 = __ldg(vb4 + j1);
        float4 v2 = __ldg(vb4 + j2);
        float4 v3 = __ldg(vb4 + j3);
        a0.x = fmaf(u0, v0.x, a0.x); a0.y = fmaf(u0, v0.y, a0.y);
        a0.z = fmaf(u0, v0.z, a0.z); a0.w = fmaf(u0, v0.w, a0.w);
        a1.x = fmaf(u1, v1.x, a1.x); a1.y = fmaf(u1, v1.y, a1.y);
        a1.z = fmaf(u1, v1.z, a1.z); a1.w = fmaf(u1, v1.w, a1.w);
        a2.x = fmaf(u2, v2.x, a2.x); a2.y = fmaf(u2, v2.y, a2.y);
        a2.z = fmaf(u2, v2.z, a2.z); a2.w = fmaf(u2, v2.w, a2.w);
        a3.x = fmaf(u3, v3.x, a3.x); a3.y = fmaf(u3, v3.y, a3.y);
        a3.z = fmaf(u3, v3.z, a3.z); a3.w = fmaf(u3, v3.w, a3.w);
    }

    float4 acc4;
    acc4.x = (a0.x + a1.x) + (a2.x + a3.x);
    acc4.y = (a0.y + a1.y) + (a2.y + a3.y);
    acc4.z = (a0.z + a1.z) + (a2.z + a3.z);
    acc4.w = (a0.w + a1.w) + (a2.w + a3.w);

    // reduce across the 4 point-subgroups
#pragma unroll
    for (int s = 8; s <= 16; s <<= 1) {
        acc4.x += __shfl_xor_sync(FULL, acc4.x, s);
        acc4.y += __shfl_xor_sync(FULL, acc4.y, s);
        acc4.z += __shfl_xor_sync(FULL, acc4.z, s);
        acc4.w += __shfl_xor_sync(FULL, acc4.w, s);
    }

    if (lane < 8)
        ((float4*)(out + (size_t)nq * DM + h * DH))[lane] = acc4;
}

// ---------------- launch ----------------
extern "C" void kernel_launch(void* const* d_in, const int* in_sizes, int n_in,
                              void* d_out, int out_size)
{
    const float* query   = (const float*)d_in[0];
    const float* refp    = (const float*)d_in[2];
    const float* in_flat = (const float*)d_in[3];
    const float* Wv = (const float*)d_in[6];
    const float* bv = (const float*)d_in[7];
    const float* Wo = (const float*)d_in[8];
    const float* bo = (const float*)d_in[9];
    const float* Wa = (const float*)d_in[10];
    const float* ba = (const float*)d_in[11];
    float* out = (float*)d_out;

    float* val_s; cudaGetSymbolAddress((void**)&val_s, g_value);
    float* off_s; cudaGetSymbolAddress((void**)&off_s, g_off);
    float* awl_s; cudaGetSymbolAddress((void**)&awl_s, g_awl);

    const int Mv = NB * LEN_IN;   // 119680
    const int Mq = NB * LQ;       // 20000

    GemmParams p;
    // seg0: value = input_flatten @ Wv + bv  (119680 x 256)
    p.s[0] = { in_flat, Wv, bv, val_s, Mv, DM, DM, DM / 128, 0 };
    int n0 = (DM / 128) * ((Mv + 127) / 128);                 // 1870
    // seg1: off = query @ Wo + bo  (20000 x 512)
    p.s[1] = { query, Wo, bo, off_s, Mq, NH * NL * NP * 2, DM,
               (NH * NL * NP * 2) / 128, n0 };
    int n1 = ((NH * NL * NP * 2) / 128) * ((Mq + 127) / 128); // 628
    // seg2: logits = query @ Wa + ba  (20000 x 256)
    p.s[2] = { query, Wa, ba, awl_s, Mq, NH * NL * NP, DM,
               (NH * NL * NP) / 128, n0 + n1 };
    int n2 = ((NH * NL * NP) / 128) * ((Mq + 127) / 128);     // 314

    gemm_tf32_multi<<<n0 + n1 + n2, 256>>>(p);

    {   // fused softmax + sampling
        int warps = NB * LQ * NH;
        int blocks = (warps + 7) / 8;
        msda_sample4<<<blocks, 256>>>(val_s, off_s, awl_s, refp, out);
    }
}

// round 5
// speedup vs baseline: 1.0495x; 1.0495x over previous
#include <cuda_runtime.h>
#include <cstdint>

// ---------------- problem constants ----------------
#define NB      8
#define LQ      2500
#define DM      256
#define NH      8
#define NL      4
#define NP      8
#define NZ      4
#define DH      32
#define LEN_IN  14960

// scratch
__device__ float g_value[(size_t)NB * LEN_IN * DM];           // 119680 x 256
__device__ float g_off  [(size_t)NB * LQ * NH * NL * NP * 2]; // 20000 x 512
__device__ float g_awl  [(size_t)NB * LQ * NH * NL * NP];     // 20000 x 256

__device__ __forceinline__ float to_tf32(float x) {
    float r;
    asm("cvt.rna.tf32.f32 %0, %1;" : "=f"(r) : "f"(x));
    return r;
}

__device__ __forceinline__ uint32_t smem_u32(const void* p) {
    return (uint32_t)__cvta_generic_to_shared(p);
}

__device__ __forceinline__ void cp_async16(void* dst, const void* src, bool pred) {
    int sz = pred ? 16 : 0;
    asm volatile("cp.async.ca.shared.global [%0], [%1], 16, %2;\n"
                 :: "r"(smem_u32(dst)), "l"(src), "r"(sz));
}

// ---------------- merged tf32 GEMM: 3 independent GEMMs in one launch ----------------
struct GemmSeg {
    const float* A; const float* B; const float* bias; float* C;
    int M, N, K, tilesX, blockStart;
};
struct GemmParams { GemmSeg s[3]; };

#define A_LD 20     // A smem row stride (floats)
#define B_LD 136    // B smem row stride (floats)
#define A_BUF (128 * A_LD)
#define B_BUF (16 * B_LD)

__global__ __launch_bounds__(256)
void gemm_tf32_multi(GemmParams p)
{
    __shared__ float As[2 * A_BUF];   // [buf][m][k] rows of 16 (pad 20)
    __shared__ float Bs[2 * B_BUF];   // [buf][k][n] rows of 128 (pad 136)

    const int bx = blockIdx.x;
    const int si = (bx >= p.s[1].blockStart ? 1 : 0) + (bx >= p.s[2].blockStart ? 1 : 0);
    const GemmSeg sg = p.s[si];
    const int local = bx - sg.blockStart;
    const int row0  = (local / sg.tilesX) * 128;
    const int col0  = (local % sg.tilesX) * 128;
    const int M = sg.M, N = sg.N, K = sg.K;
    const float* __restrict__ A = sg.A;
    const float* __restrict__ B = sg.B;

    const int tid   = threadIdx.x;
    const int warp  = tid >> 5;
    const int lane  = tid & 31;
    const int g     = lane >> 2;
    const int tig   = lane & 3;
    const int mrow  = (warp & 3) * 32;
    const int ncol  = (warp >> 2) * 64;

    float acc[2][8][4];
#pragma unroll
    for (int i = 0; i < 2; i++)
#pragma unroll
        for (int j = 0; j < 8; j++)
#pragma unroll
            for (int c = 0; c < 4; c++) acc[i][j][c] = 0.f;

    const int a_r0 = tid >> 2, a_c = (tid & 3) << 2;
    const int b_r0 = tid >> 5, b_c = (tid & 31) << 2;

    const int nkt = K / 16;

    auto stage = [&](int kt, int buf) {
        float* ab = As + buf * A_BUF;
        float* bb = Bs + buf * B_BUF;
#pragma unroll
        for (int i = 0; i < 2; i++) {
            int ar = a_r0 + i * 64;
            int gr = row0 + ar;
            cp_async16(&ab[ar * A_LD + a_c],
                       &A[(size_t)min(gr, M - 1) * K + kt * 16 + a_c], gr < M);
            int br = b_r0 + i * 8;
            cp_async16(&bb[br * B_LD + b_c],
                       &B[(size_t)(kt * 16 + br) * N + col0 + b_c], true);
        }
    };

    stage(0, 0);
    asm volatile("cp.async.commit_group;\n");

    for (int kt = 0; kt < nkt; kt++) {
        int cb = kt & 1;
        if (kt + 1 < nkt) stage(kt + 1, cb ^ 1);
        asm volatile("cp.async.commit_group;\n");
        asm volatile("cp.async.wait_group 1;\n");
        __syncthreads();

        const float* ab = As + cb * A_BUF;
        const float* bb = Bs + cb * B_BUF;
#pragma unroll
        for (int ks = 0; ks < 2; ks++) {
            const int k0 = ks * 8;
            uint32_t afr[2][4];
#pragma unroll
            for (int mt = 0; mt < 2; mt++) {
                int rb = mrow + mt * 16;
                afr[mt][0] = __float_as_uint(to_tf32(ab[(rb + g    ) * A_LD + k0 + tig    ]));
                afr[mt][1] = __float_as_uint(to_tf32(ab[(rb + g + 8) * A_LD + k0 + tig    ]));
                afr[mt][2] = __float_as_uint(to_tf32(ab[(rb + g    ) * A_LD + k0 + tig + 4]));
                afr[mt][3] = __float_as_uint(to_tf32(ab[(rb + g + 8) * A_LD + k0 + tig + 4]));
            }
            uint32_t bfr[8][2];
#pragma unroll
            for (int nt = 0; nt < 8; nt++) {
                int cbn = ncol + nt * 8;
                bfr[nt][0] = __float_as_uint(to_tf32(bb[(k0 + tig    ) * B_LD + cbn + g]));
                bfr[nt][1] = __float_as_uint(to_tf32(bb[(k0 + tig + 4) * B_LD + cbn + g]));
            }
#pragma unroll
            for (int mt = 0; mt < 2; mt++)
#pragma unroll
                for (int nt = 0; nt < 8; nt++) {
                    asm volatile(
                        "mma.sync.aligned.m16n8k8.row.col.f32.tf32.tf32.f32 "
                        "{%0,%1,%2,%3}, {%4,%5,%6,%7}, {%8,%9}, {%0,%1,%2,%3};"
                        : "+f"(acc[mt][nt][0]), "+f"(acc[mt][nt][1]),
                          "+f"(acc[mt][nt][2]), "+f"(acc[mt][nt][3])
                        : "r"(afr[mt][0]), "r"(afr[mt][1]),
                          "r"(afr[mt][2]), "r"(afr[mt][3]),
                          "r"(bfr[nt][0]), "r"(bfr[nt][1]));
                }
        }
        __syncthreads();
    }

    // epilogue
#pragma unroll
    for (int mt = 0; mt < 2; mt++) {
#pragma unroll
        for (int nt = 0; nt < 8; nt++) {
            int c = col0 + ncol + nt * 8 + tig * 2;
            float b0 = sg.bias[c], b1 = sg.bias[c + 1];
            int r0 = row0 + mrow + mt * 16 + g;
            if (r0 < M) {
                float2 v0 = make_float2(acc[mt][nt][0] + b0, acc[mt][nt][1] + b1);
                *(float2*)&sg.C[(size_t)r0 * N + c] = v0;
            }
            int r1 = r0 + 8;
            if (r1 < M) {
                float2 v1 = make_float2(acc[mt][nt][2] + b0, acc[mt][nt][3] + b1);
                *(float2*)&sg.C[(size_t)r1 * N + c] = v1;
            }
        }
    }
}

// ---------------- fused softmax + bilinear sampling (v5) ----------------
// One warp per (n, q, h). Gather: lane = (q4 point-subgroup) x (c8 channel quad).
// 2 independent corner accumulators, corners in pairs; register-capped so
// occupancy stays at 6 CTAs/SM (75%).
__global__ void __launch_bounds__(256, 6)
msda_sample5(const float* __restrict__ value,
             const float* __restrict__ off,
             const float* __restrict__ awl,
             const float* __restrict__ refp,
             float* __restrict__ out)
{
    const unsigned FULL = 0xffffffffu;
    int gwarp = (blockIdx.x * blockDim.x + threadIdx.x) >> 5;
    int lane  = threadIdx.x & 31;
    if (gwarp >= NB * LQ * NH) return;

    int h  = gwarp % NH;
    int nq = gwarp / NH;
    int n  = nq / LQ;

    // softmax over 32 logits (lane = point index)
    float logit = awl[(size_t)nq * (NH * NL * NP) + h * (NL * NP) + lane];
    float m = logit;
#pragma unroll
    for (int s = 16; s > 0; s >>= 1) m = fmaxf(m, __shfl_xor_sync(FULL, m, s));
    float e = __expf(logit - m);
    float ssum = e;
#pragma unroll
    for (int s = 16; s > 0; s >>= 1) ssum += __shfl_xor_sync(FULL, ssum, s);
    float aw = e / ssum;

    // per-point precompute (lane p == point p: level l = lane>>3, z = lane&3)
    float2 o2 = ((const float2*)(off + (size_t)nq * (NH * NL * NP * 2) + h * (NL * NP * 2)))[lane];
    int l = lane >> 3;
    float2 r2 = ((const float2*)(refp + (size_t)nq * NZ * 2))[lane & 3];
    int W = 176 >> l;
    int H = 64 >> l;
    int St = ((l > 0) ? 11264 : 0) + ((l > 1) ? 2816 : 0) + ((l > 2) ? 704 : 0);

    float x = fmaf(r2.x, (float)W, o2.x) - 0.5f;
    float y = fmaf(r2.y, (float)H, o2.y) - 0.5f;
    float xf = floorf(x), yf = floorf(y);
    int x0 = (int)xf, y0 = (int)yf;
    float wx = x - xf, wy = y - yf;
    float w00 = (1.f - wx) * (1.f - wy) * aw;
    float w01 = wx * (1.f - wy) * aw;
    float w10 = (1.f - wx) * wy * aw;
    float w11 = wx * wy * aw;

    bool ix0 = ((unsigned)x0       < (unsigned)W);
    bool ix1 = ((unsigned)(x0 + 1) < (unsigned)W);
    bool iy0 = ((unsigned)y0       < (unsigned)H);
    bool iy1 = ((unsigned)(y0 + 1) < (unsigned)H);

    int i00 = 0, i01 = 0, i10 = 0, i11 = 0;     // float4-granule indices
    if (ix0 && iy0) i00 = (St + y0 * W + x0) * (DM / 4);           else w00 = 0.f;
    if (ix1 && iy0) i01 = (St + y0 * W + x0 + 1) * (DM / 4);       else w01 = 0.f;
    if (ix0 && iy1) i10 = (St + (y0 + 1) * W + x0) * (DM / 4);     else w10 = 0.f;
    if (ix1 && iy1) i11 = (St + (y0 + 1) * W + x0 + 1) * (DM / 4); else w11 = 0.f;

    // gather phase: lane = q4*8 + c8
    int q4 = lane >> 3;
    int c8 = lane & 7;
    const float4* vb4 = (const float4*)(value + (size_t)n * LEN_IN * DM + h * DH) + c8;

    float4 a0 = make_float4(0.f, 0.f, 0.f, 0.f);
    float4 a1 = make_float4(0.f, 0.f, 0.f, 0.f);

#pragma unroll
    for (int pb = 0; pb < 32; pb += 4) {
        int src = pb + q4;
        {
            int   j0 = __shfl_sync(FULL, i00, src);
            int   j1 = __shfl_sync(FULL, i01, src);
            float u0 = __shfl_sync(FULL, w00, src);
            float u1 = __shfl_sync(FULL, w01, src);
            float4 v0 = __ldg(vb4 + j0);
            float4 v1 = __ldg(vb4 + j1);
            a0.x = fmaf(u0, v0.x, a0.x); a0.y = fmaf(u0, v0.y, a0.y);
            a0.z = fmaf(u0, v0.z, a0.z); a0.w = fmaf(u0, v0.w, a0.w);
            a1.x = fmaf(u1, v1.x, a1.x); a1.y = fmaf(u1, v1.y, a1.y);
            a1.z = fmaf(u1, v1.z, a1.z); a1.w = fmaf(u1, v1.w, a1.w);
        }
        {
            int   j2 = __shfl_sync(FULL, i10, src);
            int   j3 = __shfl_sync(FULL, i11, src);
            float u2 = __shfl_sync(FULL, w10, src);
            float u3 = __shfl_sync(FULL, w11, src);
            float4 v2 = __ldg(vb4 + j2);
            float4 v3 = __ldg(vb4 + j3);
            a0.x = fmaf(u2, v2.x, a0.x); a0.y = fmaf(u2, v2.y, a0.y);
            a0.z = fmaf(u2, v2.z, a0.z); a0.w = fmaf(u2, v2.w, a0.w);
            a1.x = fmaf(u3, v3.x, a1.x); a1.y = fmaf(u3, v3.y, a1.y);
            a1.z = fmaf(u3, v3.z, a1.z); a1.w = fmaf(u3, v3.w, a1.w);
        }
    }

    float4 acc4;
    acc4.x = a0.x + a1.x;
    acc4.y = a0.y + a1.y;
    acc4.z = a0.z + a1.z;
    acc4.w = a0.w + a1.w;

    // reduce across the 4 point-subgroups
#pragma unroll
    for (int s = 8; s <= 16; s <<= 1) {
        acc4.x += __shfl_xor_sync(FULL, acc4.x, s);
        acc4.y += __shfl_xor_sync(FULL, acc4.y, s);
        acc4.z += __shfl_xor_sync(FULL, acc4.z, s);
        acc4.w += __shfl_xor_sync(FULL, acc4.w, s);
    }

    if (lane < 8)
        ((float4*)(out + (size_t)nq * DM + h * DH))[lane] = acc4;
}

// ---------------- launch ----------------
extern "C" void kernel_launch(void* const* d_in, const int* in_sizes, int n_in,
                              void* d_out, int out_size)
{
    const float* query   = (const float*)d_in[0];
    const float* refp    = (const float*)d_in[2];
    const float* in_flat = (const float*)d_in[3];
    const float* Wv = (const float*)d_in[6];
    const float* bv = (const float*)d_in[7];
    const float* Wo = (const float*)d_in[8];
    const float* bo = (const float*)d_in[9];
    const float* Wa = (const float*)d_in[10];
    const float* ba = (const float*)d_in[11];
    float* out = (float*)d_out;

    float* val_s; cudaGetSymbolAddress((void**)&val_s, g_value);
    float* off_s; cudaGetSymbolAddress((void**)&off_s, g_off);
    float* awl_s; cudaGetSymbolAddress((void**)&awl_s, g_awl);

    const int Mv = NB * LEN_IN;   // 119680
    const int Mq = NB * LQ;       // 20000

    GemmParams p;
    // seg0: value = input_flatten @ Wv + bv  (119680 x 256)
    p.s[0] = { in_flat, Wv, bv, val_s, Mv, DM, DM, DM / 128, 0 };
    int n0 = (DM / 128) * ((Mv + 127) / 128);                 // 1870
    // seg1: off = query @ Wo + bo  (20000 x 512)
    p.s[1] = { query, Wo, bo, off_s, Mq, NH * NL * NP * 2, DM,
               (NH * NL * NP * 2) / 128, n0 };
    int n1 = ((NH * NL * NP * 2) / 128) * ((Mq + 127) / 128); // 628
    // seg2: logits = query @ Wa + ba  (20000 x 256)
    p.s[2] = { query, Wa, ba, awl_s, Mq, NH * NL * NP, DM,
               (NH * NL * NP) / 128, n0 + n1 };
    int n2 = ((NH * NL * NP) / 128) * ((Mq + 127) / 128);     // 314

    gemm_tf32_multi<<<n0 + n1 + n2, 256>>>(p);

    {   // fused softmax + sampling
        int warps = NB * LQ * NH;
        int blocks = (warps + 7) / 8;
        msda_sample5<<<blocks, 256>>>(val_s, off_s, awl_s, refp, out);
    }
}

// round 9
// speedup vs baseline: 1.1097x; 1.0574x over previous
#include <cuda_runtime.h>
#include <cuda_fp16.h>
#include <cstdint>

// ---------------- problem constants ----------------
#define NB      8
#define LQ      2500
#define DM      256
#define NH      8
#define NL      4
#define NP      8
#define NZ      4
#define DH      32
#define LEN_IN  14960

// scratch
__device__ float  g_value[(size_t)NB * LEN_IN * DM];           // 119680 x 256
__device__ float  g_off  [(size_t)NB * LQ * NH * NL * NP * 2]; // 20000 x 512
__device__ float  g_awl  [(size_t)NB * LQ * NH * NL * NP];     // 20000 x 256
__device__ __half g_Wvh[DM * DM];        // Wv^T as half [n][k]
__device__ __half g_Woh[(NH*NL*NP*2) * DM];
__device__ __half g_Wah[(NH*NL*NP) * DM];

__device__ __forceinline__ uint32_t smem_u32(const void* p) {
    return (uint32_t)__cvta_generic_to_shared(p);
}
__device__ __forceinline__ void cp_async16p(void* dst, const void* src, bool pred) {
    int sz = pred ? 16 : 0;
    asm volatile("cp.async.ca.shared.global [%0], [%1], 16, %2;\n"
                 :: "r"(smem_u32(dst)), "l"(src), "r"(sz));
}

// ---------------- weight transpose+convert: out[n][k] = (half)W[k][n] ----------------
struct CvtSeg { const float* W; __half* out; int tilesX; int blockStart; };
struct CvtParams { CvtSeg s[3]; };

__global__ void __launch_bounds__(256) cvt_weights(CvtParams p)
{
    __shared__ float t[32][33];
    int b = blockIdx.x;
    int si = (b >= p.s[1].blockStart ? 1 : 0) + (b >= p.s[2].blockStart ? 1 : 0);
    CvtSeg sg = p.s[si];
    int local = b - sg.blockStart;
    int bx = local % sg.tilesX, by = local / sg.tilesX;
    int N = sg.tilesX * 32;
    int tx = threadIdx.x & 31, ty = threadIdx.x >> 5;
#pragma unroll
    for (int j = 0; j < 32; j += 8)
        t[ty + j][tx] = sg.W[(size_t)(by * 32 + ty + j) * N + bx * 32 + tx];
    __syncthreads();
#pragma unroll
    for (int j = 0; j < 32; j += 8)
        sg.out[(size_t)(bx * 32 + ty + j) * DM + by * 32 + tx] = __float2half(t[tx][ty + j]);
}

// ---------------- merged fp16 tensor GEMM: 3 GEMMs in one launch ----------------
// C(MxN) = A(MxK=256) @ B + bias.  B pre-converted half [n][k].
// BM=BN=128, BK=16, 256 threads (8 warps), warp tile 32x64.
// A staged fp32 (cvt to half at fragment load), B staged half.
struct GemmSeg {
    const float* A; const __half* Bh; const float* bias; float* C;
    int M, N, tilesX, blockStart;
};
struct GemmParams { GemmSeg s[3]; };

#define A_LD   24                   // floats per A smem row (96B): optimal 2-phase LDS.64
#define A_BUF  (128 * A_LD)         // floats
#define BH_LD  16                   // halves per B smem row (32B, no pad needed)
#define BH_BUF (128 * BH_LD)        // halves

__global__ __launch_bounds__(256)
void gemm_fp16_multi(GemmParams p)
{
    __shared__ float  As[2 * A_BUF];    // 24 KB
    __shared__ __half Bs[2 * BH_BUF];   // 8 KB

    const int bx = blockIdx.x;
    const int si = (bx >= p.s[1].blockStart ? 1 : 0) + (bx >= p.s[2].blockStart ? 1 : 0);
    const GemmSeg sg = p.s[si];
    const int local = bx - sg.blockStart;
    const int row0  = (local / sg.tilesX) * 128;
    const int col0  = (local % sg.tilesX) * 128;
    const int M = sg.M, N = sg.N;
    const float*  __restrict__ A  = sg.A;
    const __half* __restrict__ Bh = sg.Bh;

    const int tid   = threadIdx.x;
    const int warp  = tid >> 5;
    const int lane  = tid & 31;
    const int g     = lane >> 2;
    const int tig   = lane & 3;
    const int mrow  = (warp & 3) * 32;
    const int ncol  = (warp >> 2) * 64;

    float acc[2][8][4];
#pragma unroll
    for (int i = 0; i < 2; i++)
#pragma unroll
        for (int j = 0; j < 8; j++)
#pragma unroll
            for (int c = 0; c < 4; c++) acc[i][j][c] = 0.f;

    // staging maps
    const int a_r = tid >> 2, a_c = (tid & 3) << 2;   // 2 chunks/thread (rows +0,+64)
    const int b_n = tid >> 1, b_c = (tid & 1) << 3;   // 1 chunk/thread (8 halves)

    auto stage = [&](int kt, int buf) {
        float*  ab = As + buf * A_BUF;
        __half* bb = Bs + buf * BH_BUF;
#pragma unroll
        for (int i = 0; i < 2; i++) {
            int r = a_r + i * 64;
            int gr = row0 + r;
            cp_async16p(&ab[r * A_LD + a_c],
                        &A[(size_t)min(gr, M - 1) * DM + kt * 16 + a_c], gr < M);
        }
        cp_async16p(&bb[b_n * BH_LD + b_c],
                    &Bh[(size_t)(col0 + b_n) * DM + kt * 16 + b_c], true);
    };

    stage(0, 0);
    asm volatile("cp.async.commit_group;\n");

    const int nkt = DM / 16;   // 16
    for (int kt = 0; kt < nkt; kt++) {
        int cb = kt & 1;
        if (kt + 1 < nkt) stage(kt + 1, cb ^ 1);
        asm volatile("cp.async.commit_group;\n");
        asm volatile("cp.async.wait_group 1;\n");
        __syncthreads();

        const float*  ab = As + cb * A_BUF;
        const __half* bb = Bs + cb * BH_BUF;

        // A fragments: fp32 -> half2 at load time
        uint32_t afr[2][4];
#pragma unroll
        for (int mt = 0; mt < 2; mt++) {
            int rb = mrow + mt * 16;
            float2 f; __half2 h;
            f = *(const float2*)&ab[(rb + g    ) * A_LD + 2 * tig    ];
            h = __floats2half2_rn(f.x, f.y); afr[mt][0] = *(uint32_t*)&h;
            f = *(const float2*)&ab[(rb + g + 8) * A_LD + 2 * tig    ];
            h = __floats2half2_rn(f.x, f.y); afr[mt][1] = *(uint32_t*)&h;
            f = *(const float2*)&ab[(rb + g    ) * A_LD + 2 * tig + 8];
            h = __floats2half2_rn(f.x, f.y); afr[mt][2] = *(uint32_t*)&h;
            f = *(const float2*)&ab[(rb + g + 8) * A_LD + 2 * tig + 8];
            h = __floats2half2_rn(f.x, f.y); afr[mt][3] = *(uint32_t*)&h;
        }
        // B fragments: contiguous half2 (k-pairs)
        uint32_t bfr[8][2];
#pragma unroll
        for (int nt = 0; nt < 8; nt++) {
            int n = ncol + nt * 8 + g;
            bfr[nt][0] = *(const uint32_t*)&bb[n * BH_LD + 2 * tig    ];
            bfr[nt][1] = *(const uint32_t*)&bb[n * BH_LD + 2 * tig + 8];
        }
#pragma unroll
        for (int mt = 0; mt < 2; mt++)
#pragma unroll
            for (int nt = 0; nt < 8; nt++) {
                asm volatile(
                    "mma.sync.aligned.m16n8k16.row.col.f32.f16.f16.f32 "
                    "{%0,%1,%2,%3}, {%4,%5,%6,%7}, {%8,%9}, {%0,%1,%2,%3};"
                    : "+f"(acc[mt][nt][0]), "+f"(acc[mt][nt][1]),
                      "+f"(acc[mt][nt][2]), "+f"(acc[mt][nt][3])
                    : "r"(afr[mt][0]), "r"(afr[mt][1]),
                      "r"(afr[mt][2]), "r"(afr[mt][3]),
                      "r"(bfr[nt][0]), "r"(bfr[nt][1]));
            }
        __syncthreads();
    }

    // epilogue
#pragma unroll
    for (int mt = 0; mt < 2; mt++) {
#pragma unroll
        for (int nt = 0; nt < 8; nt++) {
            int c = col0 + ncol + nt * 8 + tig * 2;
            float b0 = sg.bias[c], b1 = sg.bias[c + 1];
            int r0 = row0 + mrow + mt * 16 + g;
            if (r0 < M) {
                float2 v0 = make_float2(acc[mt][nt][0] + b0, acc[mt][nt][1] + b1);
                *(float2*)&sg.C[(size_t)r0 * N + c] = v0;
            }
            int r1 = r0 + 8;
            if (r1 < M) {
                float2 v1 = make_float2(acc[mt][nt][2] + b0, acc[mt][nt][3] + b1);
                *(float2*)&sg.C[(size_t)r1 * N + c] = v1;
            }
        }
    }
}

// ---------------- fused softmax + bilinear sampling (v3, best measured) ----------------
__global__ __launch_bounds__(256)
void msda_sample3(const float* __restrict__ value,
                  const float* __restrict__ off,
                  const float* __restrict__ awl,
                  const float* __restrict__ refp,
                  float* __restrict__ out)
{
    const unsigned FULL = 0xffffffffu;
    int gwarp = (blockIdx.x * blockDim.x + threadIdx.x) >> 5;
    int lane  = threadIdx.x & 31;
    if (gwarp >= NB * LQ * NH) return;

    int h  = gwarp % NH;
    int nq = gwarp / NH;
    int n  = nq / LQ;

    float logit = awl[(size_t)nq * (NH * NL * NP) + h * (NL * NP) + lane];
    float m = logit;
#pragma unroll
    for (int s = 16; s > 0; s >>= 1) m = fmaxf(m, __shfl_xor_sync(FULL, m, s));
    float e = __expf(logit - m);
    float ssum = e;
#pragma unroll
    for (int s = 16; s > 0; s >>= 1) ssum += __shfl_xor_sync(FULL, ssum, s);
    float aw = e / ssum;

    float2 o2 = ((const float2*)(off + (size_t)nq * (NH * NL * NP * 2) + h * (NL * NP * 2)))[lane];
    int l = lane >> 3;
    float2 r2 = ((const float2*)(refp + (size_t)nq * NZ * 2))[lane & 3];
    int W = 176 >> l;
    int H = 64 >> l;
    int St = ((l > 0) ? 11264 : 0) + ((l > 1) ? 2816 : 0) + ((l > 2) ? 704 : 0);

    float x = fmaf(r2.x, (float)W, o2.x) - 0.5f;
    float y = fmaf(r2.y, (float)H, o2.y) - 0.5f;
    float xf = floorf(x), yf = floorf(y);
    int x0 = (int)xf, y0 = (int)yf;
    float wx = x - xf, wy = y - yf;
    float w00 = (1.f - wx) * (1.f - wy) * aw;
    float w01 = wx * (1.f - wy) * aw;
    float w10 = (1.f - wx) * wy * aw;
    float w11 = wx * wy * aw;

    bool ix0 = ((unsigned)x0       < (unsigned)W);
    bool ix1 = ((unsigned)(x0 + 1) < (unsigned)W);
    bool iy0 = ((unsigned)y0       < (unsigned)H);
    bool iy1 = ((unsigned)(y0 + 1) < (unsigned)H);

    int i00 = 0, i01 = 0, i10 = 0, i11 = 0;
    if (ix0 && iy0) i00 = (St + y0 * W + x0) * (DM / 4);           else w00 = 0.f;
    if (ix1 && iy0) i01 = (St + y0 * W + x0 + 1) * (DM / 4);       else w01 = 0.f;
    if (ix0 && iy1) i10 = (St + (y0 + 1) * W + x0) * (DM / 4);     else w10 = 0.f;
    if (ix1 && iy1) i11 = (St + (y0 + 1) * W + x0 + 1) * (DM / 4); else w11 = 0.f;

    int q4 = lane >> 3;
    int c8 = lane & 7;
    const float4* vb4 = (const float4*)(value + (size_t)n * LEN_IN * DM + h * DH) + c8;

    float4 acc4 = make_float4(0.f, 0.f, 0.f, 0.f);
#pragma unroll
    for (int pb = 0; pb < 32; pb += 4) {
        int src = pb + q4;
        int j; float u; float4 v;

        j = __shfl_sync(FULL, i00, src); u = __shfl_sync(FULL, w00, src);
        v = __ldg(vb4 + j);
        acc4.x = fmaf(u, v.x, acc4.x); acc4.y = fmaf(u, v.y, acc4.y);
        acc4.z = fmaf(u, v.z, acc4.z); acc4.w = fmaf(u, v.w, acc4.w);

        j = __shfl_sync(FULL, i01, src); u = __shfl_sync(FULL, w01, src);
        v = __ldg(vb4 + j);
        acc4.x = fmaf(u, v.x, acc4.x); acc4.y = fmaf(u, v.y, acc4.y);
        acc4.z = fmaf(u, v.z, acc4.z); acc4.w = fmaf(u, v.w, acc4.w);

        j = __shfl_sync(FULL, i10, src); u = __shfl_sync(FULL, w10, src);
        v = __ldg(vb4 + j);
        acc4.x = fmaf(u, v.x, acc4.x); acc4.y = fmaf(u, v.y, acc4.y);
        acc4.z = fmaf(u, v.z, acc4.z); acc4.w = fmaf(u, v.w, acc4.w);

        j = __shfl_sync(FULL, i11, src); u = __shfl_sync(FULL, w11, src);
        v = __ldg(vb4 + j);
        acc4.x = fmaf(u, v.x, acc4.x); acc4.y = fmaf(u, v.y, acc4.y);
        acc4.z = fmaf(u, v.z, acc4.z); acc4.w = fmaf(u, v.w, acc4.w);
    }

#pragma unroll
    for (int s = 8; s <= 16; s <<= 1) {
        acc4.x += __shfl_xor_sync(FULL, acc4.x, s);
        acc4.y += __shfl_xor_sync(FULL, acc4.y, s);
        acc4.z += __shfl_xor_sync(FULL, acc4.z, s);
        acc4.w += __shfl_xor_sync(FULL, acc4.w, s);
    }

    if (lane < 8)
        ((float4*)(out + (size_t)nq * DM + h * DH))[lane] = acc4;
}

// ---------------- launch ----------------
extern "C" void kernel_launch(void* const* d_in, const int* in_sizes, int n_in,
                              void* d_out, int out_size)
{
    const float* query   = (const float*)d_in[0];
    const float* refp    = (const float*)d_in[2];
    const float* in_flat = (const float*)d_in[3];
    const float* Wv = (const float*)d_in[6];
    const float* bv = (const float*)d_in[7];
    const float* Wo = (const float*)d_in[8];
    const float* bo = (const float*)d_in[9];
    const float* Wa = (const float*)d_in[10];
    const float* ba = (const float*)d_in[11];
    float* out = (float*)d_out;

    float* val_s; cudaGetSymbolAddress((void**)&val_s, g_value);
    float* off_s; cudaGetSymbolAddress((void**)&off_s, g_off);
    float* awl_s; cudaGetSymbolAddress((void**)&awl_s, g_awl);
    __half* wvh;  cudaGetSymbolAddress((void**)&wvh, g_Wvh);
    __half* woh;  cudaGetSymbolAddress((void**)&woh, g_Woh);
    __half* wah;  cudaGetSymbolAddress((void**)&wah, g_Wah);

    const int Mv = NB * LEN_IN;   // 119680 = 935 * 128
    const int Mq = NB * LQ;       // 20000

    // 1) transpose + convert weights to half [n][k]
    CvtParams cp;
    cp.s[0] = { Wv, wvh, DM / 32, 0 };                                  // 8x8  = 64
    cp.s[1] = { Wo, woh, (NH*NL*NP*2) / 32, 64 };                       // 16x8 = 128
    cp.s[2] = { Wa, wah, (NH*NL*NP) / 32, 64 + 128 };                   // 8x8  = 64
    cvt_weights<<<256, 256>>>(cp);

    // 2) merged fp16 GEMMs
    GemmParams p;
    p.s[0] = { in_flat, wvh, bv, val_s, Mv, DM, DM / 128, 0 };
    int n0 = (DM / 128) * ((Mv + 127) / 128);                 // 1870
    p.s[1] = { query, woh, bo, off_s, Mq, NH * NL * NP * 2,
               (NH * NL * NP * 2) / 128, n0 };
    int n1 = ((NH * NL * NP * 2) / 128) * ((Mq + 127) / 128); // 628
    p.s[2] = { query, wah, ba, awl_s, Mq, NH * NL * NP,
               (NH * NL * NP) / 128, n0 + n1 };
    int n2 = ((NH * NL * NP) / 128) * ((Mq + 127) / 128);     // 314
    gemm_fp16_multi<<<n0 + n1 + n2, 256>>>(p);

    // 3) fused softmax + sampling
    {
        int warps = NB * LQ * NH;
        int blocks = (warps + 7) / 8;
        msda_sample3<<<blocks, 256>>>(val_s, off_s, awl_s, refp, out);
    }
}

// round 10
// speedup vs baseline: 1.1492x; 1.0356x over previous
#include <cuda_runtime.h>
#include <cuda_fp16.h>
#include <cstdint>

// ---------------- problem constants ----------------
#define NB      8
#define LQ      2500
#define DM      256
#define NH      8
#define NL      4
#define NP      8
#define NZ      4
#define DH      32
#define LEN_IN  14960

// scratch
__device__ float  g_value[(size_t)NB * LEN_IN * DM];           // 119680 x 256
__device__ float  g_off  [(size_t)NB * LQ * NH * NL * NP * 2]; // 20000 x 512
__device__ float  g_awl  [(size_t)NB * LQ * NH * NL * NP];     // 20000 x 256
__device__ __half g_Wvh[DM * DM];        // Wv^T as half [n][k], k-permuted per 16-block
__device__ __half g_Woh[(NH*NL*NP*2) * DM];
__device__ __half g_Wah[(NH*NL*NP) * DM];

__device__ __forceinline__ uint32_t smem_u32(const void* p) {
    return (uint32_t)__cvta_generic_to_shared(p);
}
__device__ __forceinline__ void cp_async16p(void* dst, const void* src, bool pred) {
    int sz = pred ? 16 : 0;
    asm volatile("cp.async.ca.shared.global [%0], [%1], 16, %2;\n"
                 :: "r"(smem_u32(dst)), "l"(src), "r"(sz));
}

// ---------------- weight transpose+convert+permute ----------------
// out[n][(k&~15) | perm(k&15)] = (half)W[k][n]
// perm packs {2t,2t+1,2t+8,2t+9} contiguously at position 4t (fp16 mma B-frag order).
struct CvtSeg { const float* W; __half* out; int tilesX; int blockStart; };
struct CvtParams { CvtSeg s[3]; };

__global__ void __launch_bounds__(256) cvt_weights(CvtParams p)
{
    __shared__ float t[32][33];
    int tx = threadIdx.x & 31, ty = threadIdx.x >> 5;
#pragma unroll 1
    for (int it = 0; it < 4; it++) {
        int b = blockIdx.x * 4 + it;
        int si = (b >= p.s[1].blockStart ? 1 : 0) + (b >= p.s[2].blockStart ? 1 : 0);
        CvtSeg sg = p.s[si];
        int local = b - sg.blockStart;
        int bx = local % sg.tilesX, by = local / sg.tilesX;
        int N = sg.tilesX * 32;
        __syncthreads();
#pragma unroll
        for (int j = 0; j < 32; j += 8)
            t[ty + j][tx] = sg.W[(size_t)(by * 32 + ty + j) * N + bx * 32 + tx];
        __syncthreads();
        int k = by * 32 + tx;
        int i = k & 15;
        int kp = (k & ~15) | (4 * ((i & 7) >> 1) + ((i >> 3) << 1) + (i & 1));
#pragma unroll
        for (int j = 0; j < 32; j += 8)
            sg.out[(size_t)(bx * 32 + ty + j) * DM + kp] = __float2half(t[tx][ty + j]);
    }
}

// ---------------- merged fp16 tensor GEMM: 3 GEMMs in one launch ----------------
// C(MxN) = A(MxK=256) @ B + bias.  B pre-converted half [n][k] (k-permuted).
// BM=BN=128, BK=16, 256 threads (8 warps), warp tile 32x64.
struct GemmSeg {
    const float* A; const __half* Bh; const float* bias; float* C;
    int M, N, tilesX, blockStart;
};
struct GemmParams { GemmSeg s[3]; };

#define A_LD   24                   // floats per A smem row
#define A_BUF  (128 * A_LD)
#define BH_LD  16                   // halves per B smem row (32B)
#define BH_BUF (128 * BH_LD)

__global__ __launch_bounds__(256)
void gemm_fp16_multi(GemmParams p)
{
    __shared__ float  As[2 * A_BUF];    // 24 KB
    __shared__ __half Bs[2 * BH_BUF];   // 8 KB

    const int bx = blockIdx.x;
    const int si = (bx >= p.s[1].blockStart ? 1 : 0) + (bx >= p.s[2].blockStart ? 1 : 0);
    const GemmSeg sg = p.s[si];
    const int local = bx - sg.blockStart;
    const int row0  = (local / sg.tilesX) * 128;
    const int col0  = (local % sg.tilesX) * 128;
    const int M = sg.M, N = sg.N;
    const float*  __restrict__ A  = sg.A;
    const __half* __restrict__ Bh = sg.Bh;

    const int tid   = threadIdx.x;
    const int warp  = tid >> 5;
    const int lane  = tid & 31;
    const int g     = lane >> 2;
    const int tig   = lane & 3;
    const int mrow  = (warp & 3) * 32;
    const int ncol  = (warp >> 2) * 64;

    float acc[2][8][4];
#pragma unroll
    for (int i = 0; i < 2; i++)
#pragma unroll
        for (int j = 0; j < 8; j++)
#pragma unroll
            for (int c = 0; c < 4; c++) acc[i][j][c] = 0.f;

    const int a_r = tid >> 2, a_c = (tid & 3) << 2;
    const int b_n = tid >> 1, b_c = (tid & 1) << 3;

    auto stage = [&](int kt, int buf) {
        float*  ab = As + buf * A_BUF;
        __half* bb = Bs + buf * BH_BUF;
#pragma unroll
        for (int i = 0; i < 2; i++) {
            int r = a_r + i * 64;
            int gr = row0 + r;
            cp_async16p(&ab[r * A_LD + a_c],
                        &A[(size_t)min(gr, M - 1) * DM + kt * 16 + a_c], gr < M);
        }
        cp_async16p(&bb[b_n * BH_LD + b_c],
                    &Bh[(size_t)(col0 + b_n) * DM + kt * 16 + b_c], true);
    };

    stage(0, 0);
    asm volatile("cp.async.commit_group;\n");

    const int nkt = DM / 16;   // 16
    for (int kt = 0; kt < nkt; kt++) {
        int cb = kt & 1;
        if (kt + 1 < nkt) stage(kt + 1, cb ^ 1);
        asm volatile("cp.async.commit_group;\n");
        asm volatile("cp.async.wait_group 1;\n");
        __syncthreads();

        const float*  ab = As + cb * A_BUF;
        const __half* bb = Bs + cb * BH_BUF;

        // A fragments: fp32 -> half2 at load time (fma pipe, otherwise idle)
        uint32_t afr[2][4];
#pragma unroll
        for (int mt = 0; mt < 2; mt++) {
            int rb = mrow + mt * 16;
            float2 f; __half2 h;
            f = *(const float2*)&ab[(rb + g    ) * A_LD + 2 * tig    ];
            h = __floats2half2_rn(f.x, f.y); afr[mt][0] = *(uint32_t*)&h;
            f = *(const float2*)&ab[(rb + g + 8) * A_LD + 2 * tig    ];
            h = __floats2half2_rn(f.x, f.y); afr[mt][1] = *(uint32_t*)&h;
            f = *(const float2*)&ab[(rb + g    ) * A_LD + 2 * tig + 8];
            h = __floats2half2_rn(f.x, f.y); afr[mt][2] = *(uint32_t*)&h;
            f = *(const float2*)&ab[(rb + g + 8) * A_LD + 2 * tig + 8];
            h = __floats2half2_rn(f.x, f.y); afr[mt][3] = *(uint32_t*)&h;
        }
        // B fragments: one LDS.64 per n-tile (k-permuted layout)
        uint32_t bfr[8][2];
#pragma unroll
        for (int nt = 0; nt < 8; nt++) {
            int n = ncol + nt * 8 + g;
            uint2 b64 = *(const uint2*)&bb[n * BH_LD + tig * 4];
            bfr[nt][0] = b64.x;
            bfr[nt][1] = b64.y;
        }
#pragma unroll
        for (int mt = 0; mt < 2; mt++)
#pragma unroll
            for (int nt = 0; nt < 8; nt++) {
                asm volatile(
                    "mma.sync.aligned.m16n8k16.row.col.f32.f16.f16.f32 "
                    "{%0,%1,%2,%3}, {%4,%5,%6,%7}, {%8,%9}, {%0,%1,%2,%3};"
                    : "+f"(acc[mt][nt][0]), "+f"(acc[mt][nt][1]),
                      "+f"(acc[mt][nt][2]), "+f"(acc[mt][nt][3])
                    : "r"(afr[mt][0]), "r"(afr[mt][1]),
                      "r"(afr[mt][2]), "r"(afr[mt][3]),
                      "r"(bfr[nt][0]), "r"(bfr[nt][1]));
            }
        __syncthreads();
    }

    // epilogue
#pragma unroll
    for (int mt = 0; mt < 2; mt++) {
#pragma unroll
        for (int nt = 0; nt < 8; nt++) {
            int c = col0 + ncol + nt * 8 + tig * 2;
            float b0 = sg.bias[c], b1 = sg.bias[c + 1];
            int r0 = row0 + mrow + mt * 16 + g;
            if (r0 < M) {
                float2 v0 = make_float2(acc[mt][nt][0] + b0, acc[mt][nt][1] + b1);
                *(float2*)&sg.C[(size_t)r0 * N + c] = v0;
            }
            int r1 = r0 + 8;
            if (r1 < M) {
                float2 v1 = make_float2(acc[mt][nt][2] + b0, acc[mt][nt][3] + b1);
                *(float2*)&sg.C[(size_t)r1 * N + c] = v1;
            }
        }
    }
}

// ---------------- fused softmax + bilinear sampling (v3, best measured) ----------------
__global__ __launch_bounds__(256)
void msda_sample3(const float* __restrict__ value,
                  const float* __restrict__ off,
                  const float* __restrict__ awl,
                  const float* __restrict__ refp,
                  float* __restrict__ out)
{
    const unsigned FULL = 0xffffffffu;
    int gwarp = (blockIdx.x * blockDim.x + threadIdx.x) >> 5;
    int lane  = threadIdx.x & 31;
    if (gwarp >= NB * LQ * NH) return;

    int h  = gwarp % NH;
    int nq = gwarp / NH;
    int n  = nq / LQ;

    float logit = awl[(size_t)nq * (NH * NL * NP) + h * (NL * NP) + lane];
    float m = logit;
#pragma unroll
    for (int s = 16; s > 0; s >>= 1) m = fmaxf(m, __shfl_xor_sync(FULL, m, s));
    float e = __expf(logit - m);
    float ssum = e;
#pragma unroll
    for (int s = 16; s > 0; s >>= 1) ssum += __shfl_xor_sync(FULL, ssum, s);
    float aw = e / ssum;

    float2 o2 = ((const float2*)(off + (size_t)nq * (NH * NL * NP * 2) + h * (NL * NP * 2)))[lane];
    int l = lane >> 3;
    float2 r2 = ((const float2*)(refp + (size_t)nq * NZ * 2))[lane & 3];
    int W = 176 >> l;
    int H = 64 >> l;
    int St = ((l > 0) ? 11264 : 0) + ((l > 1) ? 2816 : 0) + ((l > 2) ? 704 : 0);

    float x = fmaf(r2.x, (float)W, o2.x) - 0.5f;
    float y = fmaf(r2.y, (float)H, o2.y) - 0.5f;
    float xf = floorf(x), yf = floorf(y);
    int x0 = (int)xf, y0 = (int)yf;
    float wx = x - xf, wy = y - yf;
    float w00 = (1.f - wx) * (1.f - wy) * aw;
    float w01 = wx * (1.f - wy) * aw;
    float w10 = (1.f - wx) * wy * aw;
    float w11 = wx * wy * aw;

    bool ix0 = ((unsigned)x0       < (unsigned)W);
    bool ix1 = ((unsigned)(x0 + 1) < (unsigned)W);
    bool iy0 = ((unsigned)y0       < (unsigned)H);
    bool iy1 = ((unsigned)(y0 + 1) < (unsigned)H);

    int i00 = 0, i01 = 0, i10 = 0, i11 = 0;
    if (ix0 && iy0) i00 = (St + y0 * W + x0) * (DM / 4);           else w00 = 0.f;
    if (ix1 && iy0) i01 = (St + y0 * W + x0 + 1) * (DM / 4);       else w01 = 0.f;
    if (ix0 && iy1) i10 = (St + (y0 + 1) * W + x0) * (DM / 4);     else w10 = 0.f;
    if (ix1 && iy1) i11 = (St + (y0 + 1) * W + x0 + 1) * (DM / 4); else w11 = 0.f;

    int q4 = lane >> 3;
    int c8 = lane & 7;
    const float4* vb4 = (const float4*)(value + (size_t)n * LEN_IN * DM + h * DH) + c8;

    float4 acc4 = make_float4(0.f, 0.f, 0.f, 0.f);
#pragma unroll
    for (int pb = 0; pb < 32; pb += 4) {
        int src = pb + q4;
        int j; float u; float4 v;

        j = __shfl_sync(FULL, i00, src); u = __shfl_sync(FULL, w00, src);
        v = __ldg(vb4 + j);
        acc4.x = fmaf(u, v.x, acc4.x); acc4.y = fmaf(u, v.y, acc4.y);
        acc4.z = fmaf(u, v.z, acc4.z); acc4.w = fmaf(u, v.w, acc4.w);

        j = __shfl_sync(FULL, i01, src); u = __shfl_sync(FULL, w01, src);
        v = __ldg(vb4 + j);
        acc4.x = fmaf(u, v.x, acc4.x); acc4.y = fmaf(u, v.y, acc4.y);
        acc4.z = fmaf(u, v.z, acc4.z); acc4.w = fmaf(u, v.w, acc4.w);

        j = __shfl_sync(FULL, i10, src); u = __shfl_sync(FULL, w10, src);
        v = __ldg(vb4 + j);
        acc4.x = fmaf(u, v.x, acc4.x); acc4.y = fmaf(u, v.y, acc4.y);
        acc4.z = fmaf(u, v.z, acc4.z); acc4.w = fmaf(u, v.w, acc4.w);

        j = __shfl_sync(FULL, i11, src); u = __shfl_sync(FULL, w11, src);
        v = __ldg(vb4 + j);
        acc4.x = fmaf(u, v.x, acc4.x); acc4.y = fmaf(u, v.y, acc4.y);
        acc4.z = fmaf(u, v.z, acc4.z); acc4.w = fmaf(u, v.w, acc4.w);
    }

#pragma unroll
    for (int s = 8; s <= 16; s <<= 1) {
        acc4.x += __shfl_xor_sync(FULL, acc4.x, s);
        acc4.y += __shfl_xor_sync(FULL, acc4.y, s);
        acc4.z += __shfl_xor_sync(FULL, acc4.z, s);
        acc4.w += __shfl_xor_sync(FULL, acc4.w, s);
    }

    if (lane < 8)
        ((float4*)(out + (size_t)nq * DM + h * DH))[lane] = acc4;
}

// ---------------- launch ----------------
extern "C" void kernel_launch(void* const* d_in, const int* in_sizes, int n_in,
                              void* d_out, int out_size)
{
    const float* query   = (const float*)d_in[0];
    const float* refp    = (const float*)d_in[2];
    const float* in_flat = (const float*)d_in[3];
    const float* Wv = (const float*)d_in[6];
    const float* bv = (const float*)d_in[7];
    const float* Wo = (const float*)d_in[8];
    const float* bo = (const float*)d_in[9];
    const float* Wa = (const float*)d_in[10];
    const float* ba = (const float*)d_in[11];
    float* out = (float*)d_out;

    float* val_s; cudaGetSymbolAddress((void**)&val_s, g_value);
    float* off_s; cudaGetSymbolAddress((void**)&off_s, g_off);
    float* awl_s; cudaGetSymbolAddress((void**)&awl_s, g_awl);
    __half* wvh;  cudaGetSymbolAddress((void**)&wvh, g_Wvh);
    __half* woh;  cudaGetSymbolAddress((void**)&woh, g_Woh);
    __half* wah;  cudaGetSymbolAddress((void**)&wah, g_Wah);

    const int Mv = NB * LEN_IN;   // 119680 = 935 * 128
    const int Mq = NB * LQ;       // 20000

    // 1) transpose + convert + k-permute weights (4 tiles per block)
    CvtParams cp;
    cp.s[0] = { Wv, wvh, DM / 32, 0 };                                  // 64 tiles
    cp.s[1] = { Wo, woh, (NH*NL*NP*2) / 32, 64 };                       // 128 tiles
    cp.s[2] = { Wa, wah, (NH*NL*NP) / 32, 64 + 128 };                   // 64 tiles
    cvt_weights<<<64, 256>>>(cp);

    // 2) merged fp16 GEMMs
    GemmParams p;
    p.s[0] = { in_flat, wvh, bv, val_s, Mv, DM, DM / 128, 0 };
    int n0 = (DM / 128) * ((Mv + 127) / 128);                 // 1870
    p.s[1] = { query, woh, bo, off_s, Mq, NH * NL * NP * 2,
               (NH * NL * NP * 2) / 128, n0 };
    int n1 = ((NH * NL * NP * 2) / 128) * ((Mq + 127) / 128); // 628
    p.s[2] = { query, wah, ba, awl_s, Mq, NH * NL * NP,
               (NH * NL * NP) / 128, n0 + n1 };
    int n2 = ((NH * NL * NP) / 128) * ((Mq + 127) / 128);     // 314
    gemm_fp16_multi<<<n0 + n1 + n2, 256>>>(p);

    // 3) fused softmax + sampling
    {
        int warps = NB * LQ * NH;
        int blocks = (warps + 7) / 8;
        msda_sample3<<<blocks, 256>>>(val_s, off_s, awl_s, refp, out);
    }
}

// round 11
// speedup vs baseline: 1.3141x; 1.1435x over previous
#include <cuda_runtime.h>
#include <cuda_fp16.h>
#include <cstdint>

// ---------------- problem constants ----------------
#define NB      8
#define LQ      2500
#define DM      256
#define NH      8
#define NL      4
#define NP      8
#define NZ      4
#define DH      32
#define LEN_IN  14960

// scratch
__device__ __half g_value[(size_t)NB * LEN_IN * DM];           // 119680 x 256 (fp16)
__device__ float  g_off  [(size_t)NB * LQ * NH * NL * NP * 2]; // 20000 x 512
__device__ float  g_awl  [(size_t)NB * LQ * NH * NL * NP];     // 20000 x 256
__device__ __half g_Wvh[DM * DM];        // Wv^T as half [n][k], k-permuted per 16-block
__device__ __half g_Woh[(NH*NL*NP*2) * DM];
__device__ __half g_Wah[(NH*NL*NP) * DM];

__device__ __forceinline__ uint32_t smem_u32(const void* p) {
    return (uint32_t)__cvta_generic_to_shared(p);
}
__device__ __forceinline__ void cp_async16p(void* dst, const void* src, bool pred) {
    int sz = pred ? 16 : 0;
    asm volatile("cp.async.ca.shared.global [%0], [%1], 16, %2;\n"
                 :: "r"(smem_u32(dst)), "l"(src), "r"(sz));
}

// ---------------- weight transpose+convert+permute ----------------
// out[n][(k&~15) | perm(k&15)] = (half)W[k][n]
// perm packs {2t,2t+1,2t+8,2t+9} contiguously at position 4t (fp16 mma B-frag order).
struct CvtSeg { const float* W; __half* out; int tilesX; int blockStart; };
struct CvtParams { CvtSeg s[3]; };

__global__ void __launch_bounds__(256) cvt_weights(CvtParams p)
{
    __shared__ float t[32][33];
    int b = blockIdx.x;
    int si = (b >= p.s[1].blockStart ? 1 : 0) + (b >= p.s[2].blockStart ? 1 : 0);
    CvtSeg sg = p.s[si];
    int local = b - sg.blockStart;
    int bx = local % sg.tilesX, by = local / sg.tilesX;
    int N = sg.tilesX * 32;
    int tx = threadIdx.x & 31, ty = threadIdx.x >> 5;
#pragma unroll
    for (int j = 0; j < 32; j += 8)
        t[ty + j][tx] = sg.W[(size_t)(by * 32 + ty + j) * N + bx * 32 + tx];
    __syncthreads();
    int k = by * 32 + tx;
    int i = k & 15;
    int kp = (k & ~15) | (4 * ((i & 7) >> 1) + ((i >> 3) << 1) + (i & 1));
#pragma unroll
    for (int j = 0; j < 32; j += 8)
        sg.out[(size_t)(bx * 32 + ty + j) * DM + kp] = __float2half(t[tx][ty + j]);
}

// ---------------- merged fp16 tensor GEMM: 3 GEMMs in one launch ----------------
// C(MxN) = A(MxK=256) @ B + bias.  B pre-converted half [n][k] (k-permuted).
// BM=BN=128, BK=16, 256 threads (8 warps), warp tile 32x64.
// Seg 0 writes half output (Ch); segs 1,2 write float (Cf).
struct GemmSeg {
    const float* A; const __half* Bh; const float* bias;
    float* Cf; __half* Ch;
    int M, N, tilesX, blockStart;
};
struct GemmParams { GemmSeg s[3]; };

#define A_LD   24                   // floats per A smem row
#define A_BUF  (128 * A_LD)
#define BH_LD  16                   // halves per B smem row (32B)
#define BH_BUF (128 * BH_LD)

__global__ __launch_bounds__(256)
void gemm_fp16_multi(GemmParams p)
{
    __shared__ float  As[2 * A_BUF];    // 24 KB
    __shared__ __half Bs[2 * BH_BUF];   // 8 KB

    const int bx = blockIdx.x;
    const int si = (bx >= p.s[1].blockStart ? 1 : 0) + (bx >= p.s[2].blockStart ? 1 : 0);
    const GemmSeg sg = p.s[si];
    const int local = bx - sg.blockStart;
    const int row0  = (local / sg.tilesX) * 128;
    const int col0  = (local % sg.tilesX) * 128;
    const int M = sg.M, N = sg.N;
    const float*  __restrict__ A  = sg.A;
    const __half* __restrict__ Bh = sg.Bh;

    const int tid   = threadIdx.x;
    const int warp  = tid >> 5;
    const int lane  = tid & 31;
    const int g     = lane >> 2;
    const int tig   = lane & 3;
    const int mrow  = (warp & 3) * 32;
    const int ncol  = (warp >> 2) * 64;

    float acc[2][8][4];
#pragma unroll
    for (int i = 0; i < 2; i++)
#pragma unroll
        for (int j = 0; j < 8; j++)
#pragma unroll
            for (int c = 0; c < 4; c++) acc[i][j][c] = 0.f;

    const int a_r = tid >> 2, a_c = (tid & 3) << 2;
    const int b_n = tid >> 1, b_c = (tid & 1) << 3;

    auto stage = [&](int kt, int buf) {
        float*  ab = As + buf * A_BUF;
        __half* bb = Bs + buf * BH_BUF;
#pragma unroll
        for (int i = 0; i < 2; i++) {
            int r = a_r + i * 64;
            int gr = row0 + r;
            cp_async16p(&ab[r * A_LD + a_c],
                        &A[(size_t)min(gr, M - 1) * DM + kt * 16 + a_c], gr < M);
        }
        cp_async16p(&bb[b_n * BH_LD + b_c],
                    &Bh[(size_t)(col0 + b_n) * DM + kt * 16 + b_c], true);
    };

    stage(0, 0);
    asm volatile("cp.async.commit_group;\n");

    const int nkt = DM / 16;   // 16
    for (int kt = 0; kt < nkt; kt++) {
        int cb = kt & 1;
        if (kt + 1 < nkt) stage(kt + 1, cb ^ 1);
        asm volatile("cp.async.commit_group;\n");
        asm volatile("cp.async.wait_group 1;\n");
        __syncthreads();

        const float*  ab = As + cb * A_BUF;
        const __half* bb = Bs + cb * BH_BUF;

        // A fragments: fp32 -> half2 at load time (fma pipe, otherwise idle)
        uint32_t afr[2][4];
#pragma unroll
        for (int mt = 0; mt < 2; mt++) {
            int rb = mrow + mt * 16;
            float2 f; __half2 h;
            f = *(const float2*)&ab[(rb + g    ) * A_LD + 2 * tig    ];
            h = __floats2half2_rn(f.x, f.y); afr[mt][0] = *(uint32_t*)&h;
            f = *(const float2*)&ab[(rb + g + 8) * A_LD + 2 * tig    ];
            h = __floats2half2_rn(f.x, f.y); afr[mt][1] = *(uint32_t*)&h;
            f = *(const float2*)&ab[(rb + g    ) * A_LD + 2 * tig + 8];
            h = __floats2half2_rn(f.x, f.y); afr[mt][2] = *(uint32_t*)&h;
            f = *(const float2*)&ab[(rb + g + 8) * A_LD + 2 * tig + 8];
            h = __floats2half2_rn(f.x, f.y); afr[mt][3] = *(uint32_t*)&h;
        }
        // B fragments: one LDS.64 per n-tile (k-permuted layout)
        uint32_t bfr[8][2];
#pragma unroll
        for (int nt = 0; nt < 8; nt++) {
            int n = ncol + nt * 8 + g;
            uint2 b64 = *(const uint2*)&bb[n * BH_LD + tig * 4];
            bfr[nt][0] = b64.x;
            bfr[nt][1] = b64.y;
        }
#pragma unroll
        for (int mt = 0; mt < 2; mt++)
#pragma unroll
            for (int nt = 0; nt < 8; nt++) {
                asm volatile(
                    "mma.sync.aligned.m16n8k16.row.col.f32.f16.f16.f32 "
                    "{%0,%1,%2,%3}, {%4,%5,%6,%7}, {%8,%9}, {%0,%1,%2,%3};"
                    : "+f"(acc[mt][nt][0]), "+f"(acc[mt][nt][1]),
                      "+f"(acc[mt][nt][2]), "+f"(acc[mt][nt][3])
                    : "r"(afr[mt][0]), "r"(afr[mt][1]),
                      "r"(afr[mt][2]), "r"(afr[mt][3]),
                      "r"(bfr[nt][0]), "r"(bfr[nt][1]));
            }
        __syncthreads();
    }

    // epilogue
    const bool half_out = (sg.Ch != nullptr);
#pragma unroll
    for (int mt = 0; mt < 2; mt++) {
#pragma unroll
        for (int nt = 0; nt < 8; nt++) {
            int c = col0 + ncol + nt * 8 + tig * 2;
            float b0 = sg.bias[c], b1 = sg.bias[c + 1];
            int r0 = row0 + mrow + mt * 16 + g;
            int r1 = r0 + 8;
            if (half_out) {
                if (r0 < M) {
                    __half2 h = __floats2half2_rn(acc[mt][nt][0] + b0, acc[mt][nt][1] + b1);
                    *(__half2*)&sg.Ch[(size_t)r0 * N + c] = h;
                }
                if (r1 < M) {
                    __half2 h = __floats2half2_rn(acc[mt][nt][2] + b0, acc[mt][nt][3] + b1);
                    *(__half2*)&sg.Ch[(size_t)r1 * N + c] = h;
                }
            } else {
                if (r0 < M) {
                    float2 v0 = make_float2(acc[mt][nt][0] + b0, acc[mt][nt][1] + b1);
                    *(float2*)&sg.Cf[(size_t)r0 * N + c] = v0;
                }
                if (r1 < M) {
                    float2 v1 = make_float2(acc[mt][nt][2] + b0, acc[mt][nt][3] + b1);
                    *(float2*)&sg.Cf[(size_t)r1 * N + c] = v1;
                }
            }
        }
    }
}

// ---------------- fused softmax + bilinear sampling (v3 schedule, fp16 value) ----------------
__global__ __launch_bounds__(256)
void msda_sample3h(const __half* __restrict__ value,
                   const float* __restrict__ off,
                   const float* __restrict__ awl,
                   const float* __restrict__ refp,
                   float* __restrict__ out)
{
    const unsigned FULL = 0xffffffffu;
    int gwarp = (blockIdx.x * blockDim.x + threadIdx.x) >> 5;
    int lane  = threadIdx.x & 31;
    if (gwarp >= NB * LQ * NH) return;

    int h  = gwarp % NH;
    int nq = gwarp / NH;
    int n  = nq / LQ;

    float logit = awl[(size_t)nq * (NH * NL * NP) + h * (NL * NP) + lane];
    float m = logit;
#pragma unroll
    for (int s = 16; s > 0; s >>= 1) m = fmaxf(m, __shfl_xor_sync(FULL, m, s));
    float e = __expf(logit - m);
    float ssum = e;
#pragma unroll
    for (int s = 16; s > 0; s >>= 1) ssum += __shfl_xor_sync(FULL, ssum, s);
    float aw = e / ssum;

    float2 o2 = ((const float2*)(off + (size_t)nq * (NH * NL * NP * 2) + h * (NL * NP * 2)))[lane];
    int l = lane >> 3;
    float2 r2 = ((const float2*)(refp + (size_t)nq * NZ * 2))[lane & 3];
    int W = 176 >> l;
    int H = 64 >> l;
    int St = ((l > 0) ? 11264 : 0) + ((l > 1) ? 2816 : 0) + ((l > 2) ? 704 : 0);

    float x = fmaf(r2.x, (float)W, o2.x) - 0.5f;
    float y = fmaf(r2.y, (float)H, o2.y) - 0.5f;
    float xf = floorf(x), yf = floorf(y);
    int x0 = (int)xf, y0 = (int)yf;
    float wx = x - xf, wy = y - yf;
    float w00 = (1.f - wx) * (1.f - wy) * aw;
    float w01 = wx * (1.f - wy) * aw;
    float w10 = (1.f - wx) * wy * aw;
    float w11 = wx * wy * aw;

    bool ix0 = ((unsigned)x0       < (unsigned)W);
    bool ix1 = ((unsigned)(x0 + 1) < (unsigned)W);
    bool iy0 = ((unsigned)y0       < (unsigned)H);
    bool iy1 = ((unsigned)(y0 + 1) < (unsigned)H);

    // granule = 4 halves (8B); DM/4 = 64 granules per pixel
    int i00 = 0, i01 = 0, i10 = 0, i11 = 0;
    if (ix0 && iy0) i00 = (St + y0 * W + x0) * (DM / 4);           else w00 = 0.f;
    if (ix1 && iy0) i01 = (St + y0 * W + x0 + 1) * (DM / 4);       else w01 = 0.f;
    if (ix0 && iy1) i10 = (St + (y0 + 1) * W + x0) * (DM / 4);     else w10 = 0.f;
    if (ix1 && iy1) i11 = (St + (y0 + 1) * W + x0 + 1) * (DM / 4); else w11 = 0.f;

    int q4 = lane >> 3;
    int c8 = lane & 7;
    const uint2* vb = (const uint2*)(value + (size_t)n * LEN_IN * DM + h * DH) + c8;

    float4 acc4 = make_float4(0.f, 0.f, 0.f, 0.f);
#pragma unroll
    for (int pb = 0; pb < 32; pb += 4) {
        int src = pb + q4;
        int j; float u; uint2 raw; __half2 h0, h1; float2 f0, f1;

        j = __shfl_sync(FULL, i00, src); u = __shfl_sync(FULL, w00, src);
        raw = __ldg(vb + j);
        h0 = *(__half2*)&raw.x; h1 = *(__half2*)&raw.y;
        f0 = __half22float2(h0); f1 = __half22float2(h1);
        acc4.x = fmaf(u, f0.x, acc4.x); acc4.y = fmaf(u, f0.y, acc4.y);
        acc4.z = fmaf(u, f1.x, acc4.z); acc4.w = fmaf(u, f1.y, acc4.w);

        j = __shfl_sync(FULL, i01, src); u = __shfl_sync(FULL, w01, src);
        raw = __ldg(vb + j);
        h0 = *(__half2*)&raw.x; h1 = *(__half2*)&raw.y;
        f0 = __half22float2(h0); f1 = __half22float2(h1);
        acc4.x = fmaf(u, f0.x, acc4.x); acc4.y = fmaf(u, f0.y, acc4.y);
        acc4.z = fmaf(u, f1.x, acc4.z); acc4.w = fmaf(u, f1.y, acc4.w);

        j = __shfl_sync(FULL, i10, src); u = __shfl_sync(FULL, w10, src);
        raw = __ldg(vb + j);
        h0 = *(__half2*)&raw.x; h1 = *(__half2*)&raw.y;
        f0 = __half22float2(h0); f1 = __half22float2(h1);
        acc4.x = fmaf(u, f0.x, acc4.x); acc4.y = fmaf(u, f0.y, acc4.y);
        acc4.z = fmaf(u, f1.x, acc4.z); acc4.w = fmaf(u, f1.y, acc4.w);

        j = __shfl_sync(FULL, i11, src); u = __shfl_sync(FULL, w11, src);
        raw = __ldg(vb + j);
        h0 = *(__half2*)&raw.x; h1 = *(__half2*)&raw.y;
        f0 = __half22float2(h0); f1 = __half22float2(h1);
        acc4.x = fmaf(u, f0.x, acc4.x); acc4.y = fmaf(u, f0.y, acc4.y);
        acc4.z = fmaf(u, f1.x, acc4.z); acc4.w = fmaf(u, f1.y, acc4.w);
    }

#pragma unroll
    for (int s = 8; s <= 16; s <<= 1) {
        acc4.x += __shfl_xor_sync(FULL, acc4.x, s);
        acc4.y += __shfl_xor_sync(FULL, acc4.y, s);
        acc4.z += __shfl_xor_sync(FULL, acc4.z, s);
        acc4.w += __shfl_xor_sync(FULL, acc4.w, s);
    }

    // lane < 16 writes float4: lanes 0..7 -> even granules? keep original mapping:
    // lane c8 holds channels [4*c8 .. 4*c8+3] -> float4 slot c8
    if (lane < 8)
        ((float4*)(out + (size_t)nq * DM + h * DH))[lane] = acc4;
}

// ---------------- launch ----------------
extern "C" void kernel_launch(void* const* d_in, const int* in_sizes, int n_in,
                              void* d_out, int out_size)
{
    const float* query   = (const float*)d_in[0];
    const float* refp    = (const float*)d_in[2];
    const float* in_flat = (const float*)d_in[3];
    const float* Wv = (const float*)d_in[6];
    const float* bv = (const float*)d_in[7];
    const float* Wo = (const float*)d_in[8];
    const float* bo = (const float*)d_in[9];
    const float* Wa = (const float*)d_in[10];
    const float* ba = (const float*)d_in[11];
    float* out = (float*)d_out;

    __half* val_s; cudaGetSymbolAddress((void**)&val_s, g_value);
    float* off_s;  cudaGetSymbolAddress((void**)&off_s, g_off);
    float* awl_s;  cudaGetSymbolAddress((void**)&awl_s, g_awl);
    __half* wvh;   cudaGetSymbolAddress((void**)&wvh, g_Wvh);
    __half* woh;   cudaGetSymbolAddress((void**)&woh, g_Woh);
    __half* wah;   cudaGetSymbolAddress((void**)&wah, g_Wah);

    const int Mv = NB * LEN_IN;   // 119680 = 935 * 128
    const int Mq = NB * LQ;       // 20000

    // 1) transpose + convert + k-permute weights (1 tile per block)
    CvtParams cp;
    cp.s[0] = { Wv, wvh, DM / 32, 0 };                                  // 64 tiles
    cp.s[1] = { Wo, woh, (NH*NL*NP*2) / 32, 64 };                       // 128 tiles
    cp.s[2] = { Wa, wah, (NH*NL*NP) / 32, 64 + 128 };                   // 64 tiles
    cvt_weights<<<256, 256>>>(cp);

    // 2) merged fp16 GEMMs (seg0 -> half output)
    GemmParams p;
    p.s[0] = { in_flat, wvh, bv, nullptr, val_s, Mv, DM, DM / 128, 0 };
    int n0 = (DM / 128) * ((Mv + 127) / 128);                 // 1870
    p.s[1] = { query, woh, bo, off_s, nullptr, Mq, NH * NL * NP * 2,
               (NH * NL * NP * 2) / 128, n0 };
    int n1 = ((NH * NL * NP * 2) / 128) * ((Mq + 127) / 128); // 628
    p.s[2] = { query, wah, ba, awl_s, nullptr, Mq, NH * NL * NP,
               (NH * NL * NP) / 128, n0 + n1 };
    int n2 = ((NH * NL * NP) / 128) * ((Mq + 127) / 128);     // 314
    gemm_fp16_multi<<<n0 + n1 + n2, 256>>>(p);

    // 3) fused softmax + sampling (fp16 value)
    {
        int warps = NB * LQ * NH;
        int blocks = (warps + 7) / 8;
        msda_sample3h<<<blocks, 256>>>(val_s, off_s, awl_s, refp, out);
    }
}